// round 10
// baseline (speedup 1.0000x reference)
#include <cuda_runtime.h>
#include <cstdint>

// Chamfer distance via exact grid NN search.
// pred/gt: [4, 8192, 3] fp32, N(0,1). Output: scalar fp32.
//
// R7: (a) whole build (zero+count+scan+scatter) fused into ONE kernel with a
// 128KB smem histogram per grid (8 blocks); (b) query prunes neighbor cells
// with exact per-axis slab bounds after scanning the own cell (typical NN
// dist 0.068 << h=0.375 -> most of the 27-cell cube provably skippable);
// (c) per-warp fixed-point integer atomicAdd reduction (deterministic),
// final scalar conversion is a 1-thread kernel. 6 launches -> 3.

#define NPTS   8192
#define BATCH  4
#define NGRIDS 8                     // batch x {pred,gt}
#define GB     32
#define GB3    (GB * GB * GB)        // 32768
#define SROW   (GB3 + 4)             // row stride, %4==0 -> int4 aligned
#define XMIN   (-6.0f)
#define H      0.375f                // 12/32, exactly representable
#define INVH   (GB / 12.0f)
#define RBSAFE 0.37495f              // slightly < H: conservative cube bound
#define NQ     (2 * BATCH * NPTS)    // 65536
#define SCALE  4294967296.0          // 2^32 fixed-point for the sum

__device__ int                g_start[NGRIDS][SROW];
__device__ float4             g_pts[NGRIDS][NPTS];
__device__ unsigned long long g_sum;

__device__ __forceinline__ int bin1(float v) {
    int c = (int)floorf((v - XMIN) * INVH);
    return min(GB - 1, max(0, c));
}

// ---- K1: fused build. One block per grid: smem histogram -> scan -> CSR ----
__global__ __launch_bounds__(1024, 1)
void cd_build(const float* __restrict__ pred, const float* __restrict__ gt) {
    extern __shared__ int cnt[];            // GB3 ints = 128 KB
    __shared__ int sh[1024];
    const int g   = blockIdx.x;             // 0..7 = (b<<1)|src
    const int tid = threadIdx.x;
    const int s_  = g & 1, b = g >> 1;
    const float* src = (s_ ? gt : pred) + (size_t)b * NPTS * 3;

    for (int i = tid; i < GB3; i += 1024) cnt[i] = 0;
    if (g == 0 && tid == 0) g_sum = 0ull;
    __syncthreads();

    // count (stash cell ids for the scatter pass)
    int cells[NPTS / 1024];
    #pragma unroll
    for (int k = 0; k < NPTS / 1024; k++) {
        int i = tid + k * 1024;
        const float* p = src + (size_t)i * 3;
        int cx = bin1(p[0]), cy = bin1(p[1]), cz = bin1(p[2]);
        cells[k] = (cz * GB + cy) * GB + cx;
        atomicAdd(&cnt[cells[k]], 1);
    }
    __syncthreads();

    // block-wide exclusive scan: 32 cells per thread (int4 x8)
    int s = 0;
    #pragma unroll
    for (int k = 0; k < 8; k++) {
        int4 c4 = ((int4*)cnt)[tid * 8 + k];
        s += c4.x + c4.y + c4.z + c4.w;
    }
    sh[tid] = s;
    __syncthreads();
    #pragma unroll
    for (int off = 1; off < 1024; off <<= 1) {
        int v = (tid >= off) ? sh[tid - off] : 0;
        __syncthreads();
        sh[tid] += v;
        __syncthreads();
    }
    int run = (tid > 0) ? sh[tid - 1] : 0;

    // rewrite smem counts -> exclusive starts (= scatter cursors), mirror to gmem
    int4* gst = (int4*)&g_start[g][tid * 32];   // SROW%4==0 -> aligned
    #pragma unroll
    for (int k = 0; k < 8; k++) {
        int4 c4 = ((int4*)cnt)[tid * 8 + k];
        int4 o;
        o.x = run;
        o.y = o.x + c4.x;
        o.z = o.y + c4.y;
        o.w = o.z + c4.z;
        run = o.w + c4.w;
        gst[k] = o;
        ((int4*)cnt)[tid * 8 + k] = o;
    }
    if (tid == 1023) g_start[g][GB3] = run;     // == NPTS
    __syncthreads();

    // scatter (reload coords; L1/L2-hot)
    #pragma unroll
    for (int k = 0; k < NPTS / 1024; k++) {
        int i = tid + k * 1024;
        const float* p = src + (size_t)i * 3;
        float x = p[0], y = p[1], z = p[2];
        int pos = atomicAdd(&cnt[cells[k]], 1);
        g_pts[g][pos] = make_float4(x, y, z, 0.0f);
    }
}

// ---- K2: exact NN per query (cell-sorted order) + slab-bound pruning ----
__global__ __launch_bounds__(256)
void cd_query() {
    int t = blockIdx.x * blockDim.x + threadIdx.x;   // 65536
    int i = t & (NPTS - 1);
    int b = (t >> 13) & (BATCH - 1);
    int dir = t >> 15;

    const int qg = (b << 1) | dir;          // query grid (sorted copy of own set)
    const int dg = qg ^ 1;                  // database grid (opposite set)

    float4 qv = g_pts[qg][i];
    const float qx = qv.x, qy = qv.y, qz = qv.z;
    const int cx = bin1(qx), cy = bin1(qy), cz = bin1(qz);

    const int*    start = g_start[dg];
    const float4* pts   = g_pts[dg];

    float best = __int_as_float(0x7F800000);

    auto scan_span = [&](int s, int e) {
        for (int k = s; k < e; k++) {
            float4 p = __ldg(&pts[k]);
            float dx = qx - p.x, dy = qy - p.y, dz = qz - p.z;
            best = fminf(best, fmaf(dx, dx, fmaf(dy, dy, dz * dz)));
        }
    };

    const int cb = (cz * GB + cy) * GB;

    // own cell first: shrinks best before any pruning decision
    scan_span(__ldg(&start[cb + cx]), __ldg(&start[cb + cx + 1]));

    // per-axis squared gaps to the 6 cell faces (valid for clamped points too:
    // out-of-box points are strictly farther than the face bound)
    const float x0 = XMIN + cx * H, y0 = XMIN + cy * H, z0 = XMIN + cz * H;
    const float gxl = (qx - x0) * (qx - x0), gxr = (x0 + H - qx) * (x0 + H - qx);
    const float gyl = (qy - y0) * (qy - y0), gyr = (y0 + H - qy) * (y0 + H - qy);
    const float gzl = (qz - z0) * (qz - z0), gzr = (z0 + H - qz) * (z0 + H - qz);

    // radius-1 cube, row-merged, pruned by exact slab bounds.
    // skipping a cell whose min-d^2 >= current best can never change the final
    // min (its points are >= best-at-skip >= final best away).
    #pragma unroll
    for (int j = 0; j < 9; j++) {
        const int oy = j % 3 - 1, oz = j / 3 - 1;
        const int y = cy + oy, z = cz + oz;
        if ((unsigned)y >= GB || (unsigned)z >= GB) continue;
        const float rowb = (oy < 0 ? gyl : oy > 0 ? gyr : 0.0f)
                         + (oz < 0 ? gzl : oz > 0 ? gzr : 0.0f);
        if (rowb >= best) continue;
        if (oy == 0 && oz == 0) {
            // own row: own cell already done; x-neighbors individually
            if (cx > 0      && gxl < best) scan_span(__ldg(&start[cb + cx - 1]), __ldg(&start[cb + cx]));
            if (cx < GB - 1 && gxr < best) scan_span(__ldg(&start[cb + cx + 1]), __ldg(&start[cb + cx + 2]));
            continue;
        }
        const int rb = (z * GB + y) * GB;
        const int xa = (cx > 0      && gxl + rowb < best) ? cx - 1 : cx;
        const int xb = (cx < GB - 1 && gxr + rowb < best) ? cx + 1 : cx;
        scan_span(__ldg(&start[rb + xa]), __ldg(&start[rb + xb + 1]));
    }

    // rare tail: expand full cube until the exact Chebyshev bound holds
    int r = 1;
    float rbound = RBSAFE;
    while (best > rbound * rbound && r < GB) {
        r++;
        rbound = (float)r * RBSAFE;
        const int z0i = max(cz - r, 0), z1i = min(cz + r, GB - 1);
        const int y0i = max(cy - r, 0), y1i = min(cy + r, GB - 1);
        const int xa = max(cx - r, 0), xb = min(cx + r, GB - 1);
        for (int z = z0i; z <= z1i; z++)
            for (int y = y0i; y <= y1i; y++) {
                const int rb = (z * GB + y) * GB;
                scan_span(__ldg(&start[rb + xa]), __ldg(&start[rb + xb + 1]));
            }
    }

    // deterministic fixed-point reduction: warp-sum -> one integer RED per warp
    unsigned long long v = (unsigned long long)((double)best * SCALE + 0.5);
    #pragma unroll
    for (int off = 16; off > 0; off >>= 1)
        v += __shfl_down_sync(0xFFFFFFFFu, v, off);
    if ((threadIdx.x & 31) == 0)
        atomicAdd(&g_sum, v);
}

// ---- K3: scalar conversion ----
__global__ void cd_final(float* __restrict__ out) {
    out[0] = (float)((double)g_sum / (SCALE * (double)(BATCH * NPTS)));
}

extern "C" void kernel_launch(void* const* d_in, const int* in_sizes, int n_in,
                              void* d_out, int out_size) {
    const float* pred = (const float*)d_in[0];
    const float* gt   = (const float*)d_in[1];
    float* out        = (float*)d_out;

    static int configured = 0;
    if (!configured) {
        cudaFuncSetAttribute(cd_build, cudaFuncAttributeMaxDynamicSharedMemorySize,
                             GB3 * (int)sizeof(int));
        configured = 1;
    }

    cd_build<<<NGRIDS, 1024, GB3 * sizeof(int)>>>(pred, gt);
    cd_query<<<NQ / 256, 256>>>();
    cd_final<<<1, 1>>>(out);
}

// round 11
// speedup vs baseline: 1.0410x; 1.0410x over previous
#include <cuda_runtime.h>
#include <cstdint>

// Chamfer distance via exact grid NN search.
// pred/gt: [4, 8192, 3] fp32, N(0,1). Output: scalar fp32.
//
// R10: (a) build scan rewritten shfl-based (2 barriers instead of 40);
// (b) query batches ALL 18 radius-1 row descriptors upfront (MLP=18, one L2
// latency) and prunes rows with exact slab bounds using the already-loaded
// values -- R7 had serialized desc->scan->desc chains; (c) 4-launch graph
// [build, zero_sum, query, final] so ncu's fixed capture slot (launch idx 6,
// 6 mod 4 = 2) lands on cd_query next round.

#define NPTS   8192
#define BATCH  4
#define NGRIDS 8                     // batch x {pred,gt}
#define GB     32
#define GB3    (GB * GB * GB)        // 32768
#define SROW   (GB3 + 4)             // row stride, %4==0 -> int4 aligned
#define XMIN   (-6.0f)
#define H      0.375f                // 12/32, exactly representable
#define INVH   (GB / 12.0f)
#define RBSAFE 0.37495f              // slightly < H: conservative cube bound
#define NQ     (2 * BATCH * NPTS)    // 65536
#define SCALE  4294967296.0          // 2^32 fixed-point for the sum

__device__ int                g_start[NGRIDS][SROW];
__device__ float4             g_pts[NGRIDS][NPTS];
__device__ unsigned long long g_sum;

__device__ __forceinline__ int bin1(float v) {
    int c = (int)floorf((v - XMIN) * INVH);
    return min(GB - 1, max(0, c));
}

// ---- K1: fused build. One block per grid: smem histogram -> scan -> CSR ----
__global__ __launch_bounds__(1024, 1)
void cd_build(const float* __restrict__ pred, const float* __restrict__ gt) {
    extern __shared__ int cnt[];            // GB3 ints = 128 KB
    __shared__ int warp_part[32];
    const int g   = blockIdx.x;             // 0..7 = (b<<1)|src
    const int tid = threadIdx.x;
    const int lid = tid & 31, wid = tid >> 5;
    const int s_  = g & 1, b = g >> 1;
    const float* src = (s_ ? gt : pred) + (size_t)b * NPTS * 3;

    #pragma unroll
    for (int k = 0; k < 8; k++)
        ((int4*)cnt)[tid + k * 1024] = make_int4(0, 0, 0, 0);
    __syncthreads();

    // count (stash cell ids for the scatter pass)
    int cells[NPTS / 1024];
    #pragma unroll
    for (int k = 0; k < NPTS / 1024; k++) {
        int i = tid + k * 1024;
        const float* p = src + (size_t)i * 3;
        int cx = bin1(p[0]), cy = bin1(p[1]), cz = bin1(p[2]);
        cells[k] = (cz * GB + cy) * GB + cx;
        atomicAdd(&cnt[cells[k]], 1);
    }
    __syncthreads();

    // block-wide exclusive scan of per-thread sums (32 cells each), shfl-based
    int s = 0;
    int4 c4s[8];
    #pragma unroll
    for (int k = 0; k < 8; k++) {
        c4s[k] = ((int4*)cnt)[tid * 8 + k];
        s += c4s[k].x + c4s[k].y + c4s[k].z + c4s[k].w;
    }
    int incl = s;
    #pragma unroll
    for (int off = 1; off < 32; off <<= 1) {
        int v = __shfl_up_sync(0xFFFFFFFFu, incl, off);
        if (lid >= off) incl += v;
    }
    if (lid == 31) warp_part[wid] = incl;
    __syncthreads();
    if (wid == 0) {
        int w = warp_part[lid];
        int wincl = w;
        #pragma unroll
        for (int off = 1; off < 32; off <<= 1) {
            int v = __shfl_up_sync(0xFFFFFFFFu, wincl, off);
            if (lid >= off) wincl += v;
        }
        warp_part[lid] = wincl - w;              // exclusive warp offsets
    }
    __syncthreads();
    int run = warp_part[wid] + (incl - s);       // exclusive prefix for this thread

    // rewrite smem counts -> exclusive starts (= scatter cursors), mirror to gmem
    int4* gst = (int4*)&g_start[g][tid * 32];    // SROW%4==0 -> aligned
    #pragma unroll
    for (int k = 0; k < 8; k++) {
        int4 c4 = c4s[k];
        int4 o;
        o.x = run;
        o.y = o.x + c4.x;
        o.z = o.y + c4.y;
        o.w = o.z + c4.z;
        run = o.w + c4.w;
        gst[k] = o;
        ((int4*)cnt)[tid * 8 + k] = o;
    }
    if (tid == 1023) g_start[g][GB3] = run;      // == NPTS
    __syncthreads();

    // scatter (reload coords; L1/L2-hot)
    #pragma unroll
    for (int k = 0; k < NPTS / 1024; k++) {
        int i = tid + k * 1024;
        const float* p = src + (size_t)i * 3;
        float x = p[0], y = p[1], z = p[2];
        int pos = atomicAdd(&cnt[cells[k]], 1);
        g_pts[g][pos] = make_float4(x, y, z, 0.0f);
    }
}

// ---- K2: zero the accumulator (also pads the graph so ncu samples cd_query) ----
__global__ void cd_zero_sum() { g_sum = 0ull; }

// ---- K3: exact NN per query; all 18 descriptors batched, then slab pruning ----
__global__ __launch_bounds__(256)
void cd_query() {
    int t = blockIdx.x * blockDim.x + threadIdx.x;   // 65536
    int i = t & (NPTS - 1);
    int b = (t >> 13) & (BATCH - 1);
    int dir = t >> 15;

    const int qg = (b << 1) | dir;          // query grid (sorted copy of own set)
    const int dg = qg ^ 1;                  // database grid (opposite set)

    float4 qv = g_pts[qg][i];
    const float qx = qv.x, qy = qv.y, qz = qv.z;
    const int cx = bin1(qx), cy = bin1(qy), cz = bin1(qz);

    const int*    start = g_start[dg];
    const float4* pts   = g_pts[dg];

    float m0 = __int_as_float(0x7F800000);
    float m1 = __int_as_float(0x7F800000);

    auto scan_span = [&](int s, int e) {
        int k = s;
        for (; k + 1 < e; k += 2) {
            float4 p = __ldg(&pts[k]);
            float4 q = __ldg(&pts[k + 1]);
            float dx = qx - p.x, dy = qy - p.y, dz = qz - p.z;
            m0 = fminf(m0, fmaf(dx, dx, fmaf(dy, dy, dz * dz)));
            float ex = qx - q.x, ey = qy - q.y, ez = qz - q.z;
            m1 = fminf(m1, fmaf(ex, ex, fmaf(ey, ey, ez * ez)));
        }
        if (k < e) {
            float4 p = __ldg(&pts[k]);
            float dx = qx - p.x, dy = qy - p.y, dz = qz - p.z;
            m0 = fminf(m0, fmaf(dx, dx, fmaf(dy, dy, dz * dz)));
        }
    };

    // ---- batch ALL radius-1 descriptors upfront: 20 independent loads ----
    const int xa = max(cx - 1, 0);
    const int xb = min(cx + 1, GB - 1);
    const int cb = (cz * GB + cy) * GB;
    int s_[9], e_[9];
    #pragma unroll
    for (int j = 0; j < 9; j++) {
        int y = cy + (j % 3) - 1;
        int z = cz + (j / 3) - 1;
        bool ok = ((unsigned)y < GB) & ((unsigned)z < GB);
        int base = (z * GB + y) * GB;
        s_[j] = ok ? __ldg(&start[base + xa])     : 0;
        e_[j] = ok ? __ldg(&start[base + xb + 1]) : 0;
    }
    int so = __ldg(&start[cb + cx]), eo = __ldg(&start[cb + cx + 1]);

    // own cell first: establishes best before pruning decisions
    scan_span(so, eo);
    float best = fminf(m0, m1);

    // per-axis squared gaps to the 6 cell faces (clamped points lie beyond)
    const float x0 = XMIN + cx * H, y0 = XMIN + cy * H, z0 = XMIN + cz * H;
    const float gxl = (qx - x0) * (qx - x0), gxr = (x0 + H - qx) * (x0 + H - qx);
    const float gyl = (qy - y0) * (qy - y0), gyr = (y0 + H - qy) * (y0 + H - qy);
    const float gzl = (qz - z0) * (qz - z0), gzr = (z0 + H - qz) * (z0 + H - qz);

    // radius-1 rows, pruned by exact slab bounds (descriptors already resident).
    // Skipping a cell with min-d^2 >= best-at-skip can never change the min.
    #pragma unroll
    for (int j = 0; j < 9; j++) {
        const int oy = j % 3 - 1, oz = j / 3 - 1;
        const float rowb = (oy < 0 ? gyl : oy > 0 ? gyr : 0.0f)
                         + (oz < 0 ? gzl : oz > 0 ? gzr : 0.0f);
        if (rowb >= best) continue;
        if (oy == 0 && oz == 0) {
            if (cx > 0      && gxl < best) scan_span(s_[4], so);       // left nbr
            if (cx < GB - 1 && gxr < best) scan_span(eo, e_[4]);       // right nbr
        } else {
            scan_span(s_[j], e_[j]);
        }
        best = fminf(m0, m1);
    }

    // rare tail: expand full cube until the exact Chebyshev bound holds
    int r = 1;
    float rbound = RBSAFE;
    while (best > rbound * rbound && r < GB) {
        r++;
        rbound = (float)r * RBSAFE;
        const int z0i = max(cz - r, 0), z1i = min(cz + r, GB - 1);
        const int y0i = max(cy - r, 0), y1i = min(cy + r, GB - 1);
        const int xra = max(cx - r, 0), xrb = min(cx + r, GB - 1);
        for (int z = z0i; z <= z1i; z++)
            for (int y = y0i; y <= y1i; y++) {
                const int rb = (z * GB + y) * GB;
                scan_span(__ldg(&start[rb + xra]), __ldg(&start[rb + xrb + 1]));
            }
        best = fminf(m0, m1);
    }

    // deterministic fixed-point reduction: warp-sum -> one integer RED per warp
    unsigned long long v = (unsigned long long)((double)best * SCALE + 0.5);
    #pragma unroll
    for (int off = 16; off > 0; off >>= 1)
        v += __shfl_down_sync(0xFFFFFFFFu, v, off);
    if ((threadIdx.x & 31) == 0)
        atomicAdd(&g_sum, v);
}

// ---- K4: scalar conversion ----
__global__ void cd_final(float* __restrict__ out) {
    out[0] = (float)((double)g_sum / (SCALE * (double)(BATCH * NPTS)));
}

extern "C" void kernel_launch(void* const* d_in, const int* in_sizes, int n_in,
                              void* d_out, int out_size) {
    const float* pred = (const float*)d_in[0];
    const float* gt   = (const float*)d_in[1];
    float* out        = (float*)d_out;

    static int configured = 0;
    if (!configured) {
        cudaFuncSetAttribute(cd_build, cudaFuncAttributeMaxDynamicSharedMemorySize,
                             GB3 * (int)sizeof(int));
        configured = 1;
    }

    cd_build<<<NGRIDS, 1024, GB3 * sizeof(int)>>>(pred, gt);
    cd_zero_sum<<<1, 1>>>();
    cd_query<<<NQ / 256, 256>>>();
    cd_final<<<1, 1>>>(out);
}